// round 13
// baseline (speedup 1.0000x reference)
#include <cuda_runtime.h>
#include <cuda_bf16.h>
#include <cstdint>

#define BB 512
#define RR 264
#define KK 32
#define SS 9
#define NTHREADS 288
#define NWARPS 9
#define SROWB 144                  // operand row stride (bytes), conflict-free ldmatrix
#define NPAD 288                   // padded rows
#define OPBYTES (NPAD * SROWB)     // 41472
#define SSTF 40                    // stage row stride (floats) -> conflict-free STS.64
#define STAGEB (NWARPS * 32 * SSTF * 4) // 46080
#define SMEM_TOTAL (OPBYTES + RR * 8 + SS * KK * 4 + STAGEB)

__device__ __constant__ int   c_ends[SS]  = {28, 58, 92, 121, 150, 180, 210, 240, 264};
__device__ __constant__ float c_sizes[SS] = {28.f, 30.f, 34.f, 29.f, 29.f, 30.f, 30.f, 30.f, 24.f};

__device__ __forceinline__ uint32_t smem_u32(const void* p) {
    uint32_t a;
    asm("{ .reg .u64 t; cvta.to.shared.u64 t, %1; cvt.u32.u64 %0, t; }" : "=r"(a) : "l"(p));
    return a;
}
__device__ __forceinline__ void ldsm4(uint32_t* r, uint32_t addr) {
    asm volatile("ldmatrix.sync.aligned.m8n8.x4.shared.b16 {%0,%1,%2,%3}, [%4];"
        : "=r"(r[0]), "=r"(r[1]), "=r"(r[2]), "=r"(r[3]) : "r"(addr));
}
__device__ __forceinline__ void mma16816(float* d, const uint32_t* a, uint32_t b0, uint32_t b1) {
    asm volatile(
        "mma.sync.aligned.m16n8k16.row.col.f32.bf16.bf16.f32 "
        "{%0,%1,%2,%3}, {%4,%5,%6,%7}, {%8,%9}, {%0,%1,%2,%3};"
        : "+f"(d[0]), "+f"(d[1]), "+f"(d[2]), "+f"(d[3])
        : "r"(a[0]), "r"(a[1]), "r"(a[2]), "r"(a[3]), "r"(b0), "r"(b1));
}
__device__ __forceinline__ uint32_t packbf(float a, float b) {
    unsigned short ua = __bfloat16_as_ushort(__float2bfloat16(a));
    unsigned short ub = __bfloat16_as_ushort(__float2bfloat16(b));
    return (uint32_t)ua | ((uint32_t)ub << 16);
}

extern "C" __global__ void __launch_bounds__(NTHREADS, 2)
gram_mma(const float* __restrict__ E, float* __restrict__ out)
{
    float* intra = out;
    float* inter = out + (size_t)BB * RR * RR;
    float* adj   = inter + (size_t)BB * SS * SS;

    extern __shared__ unsigned char dyn[];
    unsigned char* sOp   = dyn;                                  // [NPAD][SROWB]: hi 64B | lo 64B
    int2*          sLoHi = (int2*)(dyn + OPBYTES);
    float*         sSum  = (float*)(dyn + OPBYTES + RR * 8);
    float*         sStg  = (float*)(dyn + OPBYTES + RR * 8 + SS * KK * 4);

    const int b    = blockIdx.x;
    const int tid  = threadIdx.x;
    const int wid  = tid >> 5;
    const int lane = tid & 31;
    const float* Eb = E + (size_t)b * (RR * KK);

    // ---- fp32 -> bf16 hi|lo split into smem; zero padded rows (1 row/thread) ----
    {
        const int r = tid;
        unsigned char* dst = sOp + r * SROWB;
        if (r < RR) {
            const float4* src = reinterpret_cast<const float4*>(Eb + r * KK);
            uint32_t h[16], l[16];
            #pragma unroll
            for (int q = 0; q < 8; q++) {
                float4 v = src[q];
                uint32_t h01 = packbf(v.x, v.y);
                uint32_t h23 = packbf(v.z, v.w);
                float rx = v.x - __bfloat162float(__ushort_as_bfloat16((unsigned short)(h01 & 0xffff)));
                float ry = v.y - __bfloat162float(__ushort_as_bfloat16((unsigned short)(h01 >> 16)));
                float rz = v.z - __bfloat162float(__ushort_as_bfloat16((unsigned short)(h23 & 0xffff)));
                float rw = v.w - __bfloat162float(__ushort_as_bfloat16((unsigned short)(h23 >> 16)));
                h[2 * q] = h01; h[2 * q + 1] = h23;
                l[2 * q] = packbf(rx, ry); l[2 * q + 1] = packbf(rz, rw);
            }
            #pragma unroll
            for (int q = 0; q < 4; q++) {
                *reinterpret_cast<uint4*>(dst + 16 * q) =
                    make_uint4(h[4 * q], h[4 * q + 1], h[4 * q + 2], h[4 * q + 3]);
                *reinterpret_cast<uint4*>(dst + 64 + 16 * q) =
                    make_uint4(l[4 * q], l[4 * q + 1], l[4 * q + 2], l[4 * q + 3]);
            }
        } else {
            #pragma unroll
            for (int q = 0; q < 8; q++)
                *reinterpret_cast<uint4*>(dst + 16 * q) = make_uint4(0, 0, 0, 0);
        }
    }
    for (int r = tid; r < RR; r += NTHREADS) {
        int s = 0;
        #pragma unroll
        for (int j = 0; j < SS; j++) s += (r >= c_ends[j]) ? 1 : 0;
        int lo = (s == 0) ? 0 : c_ends[s - 1];
        sLoHi[r] = make_int2(lo, c_ends[s]);
    }
    // ---- inter segment sums (288 threads == SS*KK) ----
    {
        int s  = tid >> 5;
        int d  = tid & 31;
        int st = (s == 0) ? 0 : c_ends[s - 1];
        int en = c_ends[s];
        float a = 0.0f;
        for (int r = st; r < en; r++) a += Eb[r * KK + d];
        sSum[tid] = a;
    }
    __syncthreads();

    if (tid < SS * SS) {
        int s = tid / SS, t = tid % SS;
        float a = 0.0f;
        #pragma unroll
        for (int d = 0; d < KK; d++)
            a += sSum[s * KK + d] * sSum[t * KK + d];
        inter[(size_t)b * SS * SS + tid] = a / (c_sizes[s] * c_sizes[t]);
    }

    // ---- warp = mt strip: 32-row band, 9 col-chunks of 32 ----
    const uint32_t opBase = smem_u32(sOp);
    const int m8    = lane >> 3;
    const int rr8   = lane & 7;
    const int radd  = rr8 + ((m8 & 1) << 3);     // ldmatrix row-within-16
    const int kaddB = (m8 >> 1) << 4;            // +16B for k8..15 halves
    const int gid   = lane >> 2;
    const int tig   = lane & 3;
    const int mt    = wid;                        // 9 warps = 9 strips
    const int rbase = mt * 32;
    float* stg = sStg + wid * (32 * SSTF);

    // A fragments hoisted: 2 m16 tiles x 4 k-chunks (H0,H1,L0,L1), reused over ns
    uint32_t a[2][4][4];
    #pragma unroll
    for (int mi = 0; mi < 2; mi++) {
        uint32_t aaddr = opBase + (uint32_t)(rbase + 16 * mi + radd) * SROWB + kaddB;
        #pragma unroll
        for (int c = 0; c < 4; c++) ldsm4(a[mi][c], aaddr + c * 32);
    }

    #pragma unroll 1
    for (int ns = 0; ns < 9; ns++) {
        const int c0 = ns * 32;

        float d[2][4][4];
        #pragma unroll
        for (int mi = 0; mi < 2; mi++)
            #pragma unroll
            for (int nj = 0; nj < 4; nj++)
                #pragma unroll
                for (int p = 0; p < 4; p++) d[mi][nj][p] = 0.0f;

        #pragma unroll
        for (int bc = 0; bc < 4; bc++) {
            uint32_t bg[2][4];
            uint32_t baddr = opBase + (uint32_t)(c0 + radd) * SROWB + kaddB + bc * 32;
            ldsm4(bg[0], baddr);
            ldsm4(bg[1], baddr + 16 * SROWB);
            const int ac1 = (bc < 2) ? bc : (bc - 2);
            #pragma unroll
            for (int mi = 0; mi < 2; mi++) {
                #pragma unroll
                for (int nh = 0; nh < 2; nh++) {
                    mma16816(d[mi][2 * nh],     a[mi][ac1], bg[nh][0], bg[nh][2]);
                    mma16816(d[mi][2 * nh + 1], a[mi][ac1], bg[nh][1], bg[nh][3]);
                    if (bc < 2) {
                        mma16816(d[mi][2 * nh],     a[mi][bc + 2], bg[nh][0], bg[nh][2]);
                        mma16816(d[mi][2 * nh + 1], a[mi][bc + 2], bg[nh][1], bg[nh][3]);
                    }
                }
            }
        }

        // ---- stage fragments (conflict-free STS.64), then coalesced stores ----
        #pragma unroll
        for (int mi = 0; mi < 2; mi++) {
            #pragma unroll
            for (int nj = 0; nj < 4; nj++) {
                float2 v0; v0.x = d[mi][nj][0]; v0.y = d[mi][nj][1];
                float2 v1; v1.x = d[mi][nj][2]; v1.y = d[mi][nj][3];
                const int cc = nj * 8 + 2 * tig;
                *reinterpret_cast<float2*>(stg + (mi * 16 + gid) * SSTF + cc)     = v0;
                *reinterpret_cast<float2*>(stg + (mi * 16 + gid + 8) * SSTF + cc) = v1;
            }
        }
        __syncwarp();
        #pragma unroll
        for (int i = 0; i < 8; i++) {
            const int f  = i * 32 + lane;
            const int rl = f >> 3;
            const int q  = f & 7;
            const int rg = rbase + rl;
            const int cg = c0 + 4 * q;
            if (rg < RR && cg < RR) {
                float4 v = *reinterpret_cast<float4*>(stg + rl * SSTF + 4 * q);
                const size_t off = ((size_t)b * RR + rg) * RR + cg;
                *reinterpret_cast<float4*>(adj + off) = v;
                int2 lh = sLoHi[rg];
                float4 w;
                w.x = (cg + 0 >= lh.x && cg + 0 < lh.y) ? v.x : 0.0f;
                w.y = (cg + 1 >= lh.x && cg + 1 < lh.y) ? v.y : 0.0f;
                w.z = (cg + 2 >= lh.x && cg + 2 < lh.y) ? v.z : 0.0f;
                w.w = (cg + 3 >= lh.x && cg + 3 < lh.y) ? v.w : 0.0f;
                *reinterpret_cast<float4*>(intra + off) = w;
            }
        }
        __syncwarp();
    }
}

extern "C" void kernel_launch(void* const* d_in, const int* in_sizes, int n_in,
                              void* d_out, int out_size)
{
    (void)in_sizes; (void)n_in; (void)out_size;
    const float* E = (const float*)d_in[0];
    float* out = (float*)d_out;

    cudaFuncSetAttribute(gram_mma, cudaFuncAttributeMaxDynamicSharedMemorySize, SMEM_TOTAL);
    gram_mma<<<BB, NTHREADS, SMEM_TOTAL>>>(E, out);
}

// round 14
// speedup vs baseline: 1.1586x; 1.1586x over previous
#include <cuda_runtime.h>
#include <cuda_bf16.h>
#include <cstdint>

#define BB 512
#define RR 264
#define KK 32
#define SS 9
#define NTHREADS 288
#define NWARPS 9
#define SROWB 144                  // operand row stride (bytes), conflict-free ldmatrix
#define NPAD 288                   // padded rows
#define OPBYTES (NPAD * SROWB)     // 41472
#define SSTF 40                    // stage row stride (floats) -> conflict-free STS.64
#define STAGEB (NWARPS * 32 * SSTF * 4) // 46080
#define SMEM_TOTAL (OPBYTES + RR * 8 + SS * KK * 4 + STAGEB)

__device__ __constant__ int   c_ends[SS]  = {28, 58, 92, 121, 150, 180, 210, 240, 264};
__device__ __constant__ float c_sizes[SS] = {28.f, 30.f, 34.f, 29.f, 29.f, 30.f, 30.f, 30.f, 24.f};

__device__ __forceinline__ uint32_t smem_u32(const void* p) {
    uint32_t a;
    asm("{ .reg .u64 t; cvta.to.shared.u64 t, %1; cvt.u32.u64 %0, t; }" : "=r"(a) : "l"(p));
    return a;
}
__device__ __forceinline__ void ldsm4(uint32_t* r, uint32_t addr) {
    asm volatile("ldmatrix.sync.aligned.m8n8.x4.shared.b16 {%0,%1,%2,%3}, [%4];"
        : "=r"(r[0]), "=r"(r[1]), "=r"(r[2]), "=r"(r[3]) : "r"(addr));
}
__device__ __forceinline__ void mma16816(float* d, const uint32_t* a, uint32_t b0, uint32_t b1) {
    asm volatile(
        "mma.sync.aligned.m16n8k16.row.col.f32.bf16.bf16.f32 "
        "{%0,%1,%2,%3}, {%4,%5,%6,%7}, {%8,%9}, {%0,%1,%2,%3};"
        : "+f"(d[0]), "+f"(d[1]), "+f"(d[2]), "+f"(d[3])
        : "r"(a[0]), "r"(a[1]), "r"(a[2]), "r"(a[3]), "r"(b0), "r"(b1));
}
__device__ __forceinline__ uint32_t packbf(float a, float b) {
    unsigned short ua = __bfloat16_as_ushort(__float2bfloat16(a));
    unsigned short ub = __bfloat16_as_ushort(__float2bfloat16(b));
    return (uint32_t)ua | ((uint32_t)ub << 16);
}

extern "C" __global__ void __launch_bounds__(NTHREADS, 2)
gram_mma(const float* __restrict__ E, float* __restrict__ out)
{
    float* intra = out;
    float* inter = out + (size_t)BB * RR * RR;
    float* adj   = inter + (size_t)BB * SS * SS;

    extern __shared__ unsigned char dyn[];
    unsigned char* sOp   = dyn;                                  // [NPAD][SROWB]: hi 64B | lo 64B
    int2*          sLoHi = (int2*)(dyn + OPBYTES);
    float*         sSum  = (float*)(dyn + OPBYTES + RR * 8);
    float*         sStg  = (float*)(dyn + OPBYTES + RR * 8 + SS * KK * 4);

    const int b    = blockIdx.x;
    const int tid  = threadIdx.x;
    const int wid  = tid >> 5;
    const int lane = tid & 31;
    const float* Eb = E + (size_t)b * (RR * KK);

    // ---- fp32 -> bf16 hi|lo split into smem; zero padded rows (1 row/thread) ----
    {
        const int r = tid;
        unsigned char* dst = sOp + r * SROWB;
        if (r < RR) {
            const float4* src = reinterpret_cast<const float4*>(Eb + r * KK);
            uint32_t h[16], l[16];
            #pragma unroll
            for (int q = 0; q < 8; q++) {
                float4 v = src[q];
                uint32_t h01 = packbf(v.x, v.y);
                uint32_t h23 = packbf(v.z, v.w);
                float rx = v.x - __bfloat162float(__ushort_as_bfloat16((unsigned short)(h01 & 0xffff)));
                float ry = v.y - __bfloat162float(__ushort_as_bfloat16((unsigned short)(h01 >> 16)));
                float rz = v.z - __bfloat162float(__ushort_as_bfloat16((unsigned short)(h23 & 0xffff)));
                float rw = v.w - __bfloat162float(__ushort_as_bfloat16((unsigned short)(h23 >> 16)));
                h[2 * q] = h01; h[2 * q + 1] = h23;
                l[2 * q] = packbf(rx, ry); l[2 * q + 1] = packbf(rz, rw);
            }
            #pragma unroll
            for (int q = 0; q < 4; q++) {
                *reinterpret_cast<uint4*>(dst + 16 * q) =
                    make_uint4(h[4 * q], h[4 * q + 1], h[4 * q + 2], h[4 * q + 3]);
                *reinterpret_cast<uint4*>(dst + 64 + 16 * q) =
                    make_uint4(l[4 * q], l[4 * q + 1], l[4 * q + 2], l[4 * q + 3]);
            }
        } else {
            #pragma unroll
            for (int q = 0; q < 8; q++)
                *reinterpret_cast<uint4*>(dst + 16 * q) = make_uint4(0, 0, 0, 0);
        }
    }
    for (int r = tid; r < RR; r += NTHREADS) {
        int s = 0;
        #pragma unroll
        for (int j = 0; j < SS; j++) s += (r >= c_ends[j]) ? 1 : 0;
        int lo = (s == 0) ? 0 : c_ends[s - 1];
        sLoHi[r] = make_int2(lo, c_ends[s]);
    }
    // ---- inter segment sums (288 threads == SS*KK) ----
    {
        int s  = tid >> 5;
        int d  = tid & 31;
        int st = (s == 0) ? 0 : c_ends[s - 1];
        int en = c_ends[s];
        float a = 0.0f;
        for (int r = st; r < en; r++) a += Eb[r * KK + d];
        sSum[tid] = a;
    }
    __syncthreads();

    if (tid < SS * SS) {
        int s = tid / SS, t = tid % SS;
        float a = 0.0f;
        #pragma unroll
        for (int d = 0; d < KK; d++)
            a += sSum[s * KK + d] * sSum[t * KK + d];
        inter[(size_t)b * SS * SS + tid] = a / (c_sizes[s] * c_sizes[t]);
    }

    // ---- warp = fixed col-chunk (ns = wid); mt swept together 0..8 ----
    const uint32_t opBase = smem_u32(sOp);
    const int m8    = lane >> 3;
    const int rr8   = lane & 7;
    const int radd  = rr8 + ((m8 & 1) << 3);     // ldmatrix row-within-16
    const int kaddB = (m8 >> 1) << 4;            // +16B for k8..15 halves
    const int gid   = lane >> 2;
    const int tig   = lane & 3;
    const int c0    = wid * 32;                   // this warp's column chunk
    float* stg = sStg + wid * (32 * SSTF);

    // B fragments hoisted: 4 chunks (H0,H1,L0,L1) x 2 n16-halves, reused over all mt
    uint32_t bg[4][2][4];
    #pragma unroll
    for (int bc = 0; bc < 4; bc++) {
        uint32_t baddr = opBase + (uint32_t)(c0 + radd) * SROWB + kaddB + bc * 32;
        ldsm4(bg[bc][0], baddr);
        ldsm4(bg[bc][1], baddr + 16 * SROWB);
    }

    #pragma unroll 1
    for (int mt = 0; mt < 9; mt++) {
        const int rbase = mt * 32;

        float d[2][4][4];
        #pragma unroll
        for (int mi = 0; mi < 2; mi++)
            #pragma unroll
            for (int nj = 0; nj < 4; nj++)
                #pragma unroll
                for (int p = 0; p < 4; p++) d[mi][nj][p] = 0.0f;

        // loop over A chunks; products grouped by A-chunk (8 transient a-regs)
        #pragma unroll
        for (int ac = 0; ac < 4; ac++) {
            uint32_t a[2][4];
            #pragma unroll
            for (int mi = 0; mi < 2; mi++) {
                uint32_t aaddr = opBase + (uint32_t)(rbase + 16 * mi + radd) * SROWB
                               + kaddB + ac * 32;
                ldsm4(a[mi], aaddr);
            }
            // A hi chunks (ac<2): pair with B hi (bc=ac) and B lo (bc=ac+2)
            // A lo chunks (ac>=2): pair with B hi (bc=ac-2)
            const int bc0 = (ac < 2) ? ac : (ac - 2);
            #pragma unroll
            for (int mi = 0; mi < 2; mi++) {
                #pragma unroll
                for (int nh = 0; nh < 2; nh++) {
                    mma16816(d[mi][2 * nh],     a[mi], bg[bc0][nh][0], bg[bc0][nh][2]);
                    mma16816(d[mi][2 * nh + 1], a[mi], bg[bc0][nh][1], bg[bc0][nh][3]);
                    if (ac < 2) {
                        mma16816(d[mi][2 * nh],     a[mi], bg[ac + 2][nh][0], bg[ac + 2][nh][2]);
                        mma16816(d[mi][2 * nh + 1], a[mi], bg[ac + 2][nh][1], bg[ac + 2][nh][3]);
                    }
                }
            }
        }

        // ---- stage fragments (conflict-free STS.64), then coalesced stores ----
        #pragma unroll
        for (int mi = 0; mi < 2; mi++) {
            #pragma unroll
            for (int nj = 0; nj < 4; nj++) {
                float2 v0; v0.x = d[mi][nj][0]; v0.y = d[mi][nj][1];
                float2 v1; v1.x = d[mi][nj][2]; v1.y = d[mi][nj][3];
                const int cc = nj * 8 + 2 * tig;
                *reinterpret_cast<float2*>(stg + (mi * 16 + gid) * SSTF + cc)     = v0;
                *reinterpret_cast<float2*>(stg + (mi * 16 + gid + 8) * SSTF + cc) = v1;
            }
        }
        __syncwarp();
        #pragma unroll
        for (int i = 0; i < 8; i++) {
            const int f  = i * 32 + lane;
            const int rl = f >> 3;
            const int q  = f & 7;
            const int rg = rbase + rl;
            const int cg = c0 + 4 * q;
            if (rg < RR && cg < RR) {
                float4 v = *reinterpret_cast<float4*>(stg + rl * SSTF + 4 * q);
                const size_t off = ((size_t)b * RR + rg) * RR + cg;
                *reinterpret_cast<float4*>(adj + off) = v;
                int2 lh = sLoHi[rg];
                float4 w;
                w.x = (cg + 0 >= lh.x && cg + 0 < lh.y) ? v.x : 0.0f;
                w.y = (cg + 1 >= lh.x && cg + 1 < lh.y) ? v.y : 0.0f;
                w.z = (cg + 2 >= lh.x && cg + 2 < lh.y) ? v.z : 0.0f;
                w.w = (cg + 3 >= lh.x && cg + 3 < lh.y) ? v.w : 0.0f;
                *reinterpret_cast<float4*>(intra + off) = w;
            }
        }
        __syncwarp();
    }
}

extern "C" void kernel_launch(void* const* d_in, const int* in_sizes, int n_in,
                              void* d_out, int out_size)
{
    (void)in_sizes; (void)n_in; (void)out_size;
    const float* E = (const float*)d_in[0];
    float* out = (float*)d_out;

    cudaFuncSetAttribute(gram_mma, cudaFuncAttributeMaxDynamicSharedMemorySize, SMEM_TOTAL);
    gram_mma<<<BB, NTHREADS, SMEM_TOTAL>>>(E, out);
}

// round 15
// speedup vs baseline: 1.1642x; 1.0048x over previous
#include <cuda_runtime.h>
#include <cuda_bf16.h>
#include <cstdint>

#define BB 512
#define RR 264
#define KK 32
#define SS 9
#define NTHREADS 288
#define NWARPS 9
#define SROWB 144                  // operand row stride (bytes), conflict-free ldmatrix
#define NPAD 288                   // padded rows
#define OPBYTES (NPAD * SROWB)     // 41472
#define SMEM_TOTAL (OPBYTES + SS * KK * 4)

__device__ __constant__ int   c_ends[SS]   = {28, 58, 92, 121, 150, 180, 210, 240, 264};
__device__ __constant__ int   c_starts[SS] = {0, 28, 58, 92, 121, 150, 180, 210, 240};
__device__ __constant__ float c_sizes[SS]  = {28.f, 30.f, 34.f, 29.f, 29.f, 30.f, 30.f, 30.f, 24.f};

__device__ __forceinline__ uint32_t smem_u32(const void* p) {
    uint32_t a;
    asm("{ .reg .u64 t; cvta.to.shared.u64 t, %1; cvt.u32.u64 %0, t; }" : "=r"(a) : "l"(p));
    return a;
}
__device__ __forceinline__ void ldsm4(uint32_t* r, uint32_t addr) {
    asm volatile("ldmatrix.sync.aligned.m8n8.x4.shared.b16 {%0,%1,%2,%3}, [%4];"
        : "=r"(r[0]), "=r"(r[1]), "=r"(r[2]), "=r"(r[3]) : "r"(addr));
}
__device__ __forceinline__ void mma16816(float* d, const uint32_t* a, uint32_t b0, uint32_t b1) {
    asm volatile(
        "mma.sync.aligned.m16n8k16.row.col.f32.bf16.bf16.f32 "
        "{%0,%1,%2,%3}, {%4,%5,%6,%7}, {%8,%9}, {%0,%1,%2,%3};"
        : "+f"(d[0]), "+f"(d[1]), "+f"(d[2]), "+f"(d[3])
        : "r"(a[0]), "r"(a[1]), "r"(a[2]), "r"(a[3]), "r"(b0), "r"(b1));
}
__device__ __forceinline__ uint32_t packbf(float a, float b) {
    unsigned short ua = __bfloat16_as_ushort(__float2bfloat16(a));
    unsigned short ub = __bfloat16_as_ushort(__float2bfloat16(b));
    return (uint32_t)ua | ((uint32_t)ub << 16);
}

extern "C" __global__ void __launch_bounds__(NTHREADS, 2)
gram_mma(const float* __restrict__ E, float* __restrict__ out)
{
    float* intra = out;
    float* inter = out + (size_t)BB * RR * RR;
    float* adj   = inter + (size_t)BB * SS * SS;

    extern __shared__ unsigned char dyn[];
    unsigned char* sOp  = dyn;                                  // [NPAD][SROWB]: hi 64B | lo 64B
    float*         sSum = (float*)(dyn + OPBYTES);

    const int b    = blockIdx.x;
    const int tid  = threadIdx.x;
    const int wid  = tid >> 5;
    const int lane = tid & 31;
    const float* Eb = E + (size_t)b * (RR * KK);

    // ---- fp32 -> bf16 hi|lo split into smem; zero padded rows (1 row/thread) ----
    {
        const int r = tid;
        unsigned char* dst = sOp + r * SROWB;
        if (r < RR) {
            const float4* src = reinterpret_cast<const float4*>(Eb + r * KK);
            uint32_t h[16], l[16];
            #pragma unroll
            for (int q = 0; q < 8; q++) {
                float4 v = src[q];
                uint32_t h01 = packbf(v.x, v.y);
                uint32_t h23 = packbf(v.z, v.w);
                float rx = v.x - __bfloat162float(__ushort_as_bfloat16((unsigned short)(h01 & 0xffff)));
                float ry = v.y - __bfloat162float(__ushort_as_bfloat16((unsigned short)(h01 >> 16)));
                float rz = v.z - __bfloat162float(__ushort_as_bfloat16((unsigned short)(h23 & 0xffff)));
                float rw = v.w - __bfloat162float(__ushort_as_bfloat16((unsigned short)(h23 >> 16)));
                h[2 * q] = h01; h[2 * q + 1] = h23;
                l[2 * q] = packbf(rx, ry); l[2 * q + 1] = packbf(rz, rw);
            }
            #pragma unroll
            for (int q = 0; q < 4; q++) {
                *reinterpret_cast<uint4*>(dst + 16 * q) =
                    make_uint4(h[4 * q], h[4 * q + 1], h[4 * q + 2], h[4 * q + 3]);
                *reinterpret_cast<uint4*>(dst + 64 + 16 * q) =
                    make_uint4(l[4 * q], l[4 * q + 1], l[4 * q + 2], l[4 * q + 3]);
            }
        } else {
            #pragma unroll
            for (int q = 0; q < 8; q++)
                *reinterpret_cast<uint4*>(dst + 16 * q) = make_uint4(0, 0, 0, 0);
        }
    }
    // ---- inter segment sums (288 threads == SS*KK) ----
    {
        int s  = tid >> 5;
        int d  = tid & 31;
        int st = (s == 0) ? 0 : c_ends[s - 1];
        int en = c_ends[s];
        float a = 0.0f;
        for (int r = st; r < en; r++) a += Eb[r * KK + d];
        sSum[tid] = a;
    }
    __syncthreads();

    if (tid < SS * SS) {
        int s = tid / SS, t = tid % SS;
        float a = 0.0f;
        #pragma unroll
        for (int d = 0; d < KK; d++)
            a += sSum[s * KK + d] * sSum[t * KK + d];
        inter[(size_t)b * SS * SS + tid] = a / (c_sizes[s] * c_sizes[t]);
    }

    // ---- warp = fixed col-chunk (ns = wid); mt swept together 0..8 ----
    const uint32_t opBase = smem_u32(sOp);
    const int m8    = lane >> 3;
    const int rr8   = lane & 7;
    const int radd  = rr8 + ((m8 & 1) << 3);     // ldmatrix row-within-16
    const int kaddB = (m8 >> 1) << 4;            // +16B for k8..15 halves
    const int gid   = lane >> 2;
    const int tig   = lane & 3;
    const int c0    = wid * 32;                   // this warp's column chunk

    // register-resident per-column intra bounds + validity for this thread's 8 columns
    int lo0[4], hi0[4], lo1[4], hi1[4];
    bool cvalid[4];
    #pragma unroll
    for (int nj = 0; nj < 4; nj++) {
        const int c = c0 + 8 * nj + 2 * tig;
        cvalid[nj] = (c < RR);
        int s0 = 0, s1 = 0;
        #pragma unroll
        for (int j = 0; j < SS; j++) {
            s0 += (c     >= c_ends[j]) ? 1 : 0;
            s1 += (c + 1 >= c_ends[j]) ? 1 : 0;
        }
        s0 = min(s0, SS - 1); s1 = min(s1, SS - 1);
        lo0[nj] = c_starts[s0]; hi0[nj] = c_ends[s0];
        lo1[nj] = c_starts[s1]; hi1[nj] = c_ends[s1];
    }

    // B fragments hoisted: 4 chunks (H0,H1,L0,L1) x 2 n16-halves, reused over all mt
    uint32_t bg[4][2][4];
    #pragma unroll
    for (int bc = 0; bc < 4; bc++) {
        uint32_t baddr = opBase + (uint32_t)(c0 + radd) * SROWB + kaddB + bc * 32;
        ldsm4(bg[bc][0], baddr);
        ldsm4(bg[bc][1], baddr + 16 * SROWB);
    }

    #pragma unroll 1
    for (int mt = 0; mt < 9; mt++) {
        const int rbase = mt * 32;

        float d[2][4][4];
        #pragma unroll
        for (int mi = 0; mi < 2; mi++)
            #pragma unroll
            for (int nj = 0; nj < 4; nj++)
                #pragma unroll
                for (int p = 0; p < 4; p++) d[mi][nj][p] = 0.0f;

        #pragma unroll
        for (int ac = 0; ac < 4; ac++) {
            uint32_t a[2][4];
            #pragma unroll
            for (int mi = 0; mi < 2; mi++) {
                uint32_t aaddr = opBase + (uint32_t)(rbase + 16 * mi + radd) * SROWB
                               + kaddB + ac * 32;
                ldsm4(a[mi], aaddr);
            }
            const int bc0 = (ac < 2) ? ac : (ac - 2);
            #pragma unroll
            for (int mi = 0; mi < 2; mi++) {
                #pragma unroll
                for (int nh = 0; nh < 2; nh++) {
                    mma16816(d[mi][2 * nh],     a[mi], bg[bc0][nh][0], bg[bc0][nh][2]);
                    mma16816(d[mi][2 * nh + 1], a[mi], bg[bc0][nh][1], bg[bc0][nh][3]);
                    if (ac < 2) {
                        mma16816(d[mi][2 * nh],     a[mi], bg[ac + 2][nh][0], bg[ac + 2][nh][2]);
                        mma16816(d[mi][2 * nh + 1], a[mi], bg[ac + 2][nh][1], bg[ac + 2][nh][3]);
                    }
                }
            }
        }

        // ---- direct fragment stores: STG.64 per pair, register masks for intra ----
        #pragma unroll
        for (int mi = 0; mi < 2; mi++) {
            const int r1 = rbase + 16 * mi + gid;
            const int r2 = r1 + 8;
            const size_t ro1 = ((size_t)b * RR + r1) * RR;
            const size_t ro2 = ((size_t)b * RR + r2) * RR;
            #pragma unroll
            for (int nj = 0; nj < 4; nj++) {
                if (!cvalid[nj]) continue;
                const int cc = c0 + 8 * nj + 2 * tig;
                if (r1 < RR) {
                    float2 v; v.x = d[mi][nj][0]; v.y = d[mi][nj][1];
                    *reinterpret_cast<float2*>(adj + ro1 + cc) = v;
                    float2 w;
                    w.x = (r1 >= lo0[nj] && r1 < hi0[nj]) ? v.x : 0.0f;
                    w.y = (r1 >= lo1[nj] && r1 < hi1[nj]) ? v.y : 0.0f;
                    *reinterpret_cast<float2*>(intra + ro1 + cc) = w;
                }
                if (r2 < RR) {
                    float2 v; v.x = d[mi][nj][2]; v.y = d[mi][nj][3];
                    *reinterpret_cast<float2*>(adj + ro2 + cc) = v;
                    float2 w;
                    w.x = (r2 >= lo0[nj] && r2 < hi0[nj]) ? v.x : 0.0f;
                    w.y = (r2 >= lo1[nj] && r2 < hi1[nj]) ? v.y : 0.0f;
                    *reinterpret_cast<float2*>(intra + ro2 + cc) = w;
                }
            }
        }
    }
}

extern "C" void kernel_launch(void* const* d_in, const int* in_sizes, int n_in,
                              void* d_out, int out_size)
{
    (void)in_sizes; (void)n_in; (void)out_size;
    const float* E = (const float*)d_in[0];
    float* out = (float*)d_out;

    cudaFuncSetAttribute(gram_mma, cudaFuncAttributeMaxDynamicSharedMemorySize, SMEM_TOTAL);
    gram_mma<<<BB, NTHREADS, SMEM_TOTAL>>>(E, out);
}